// round 6
// baseline (speedup 1.0000x reference)
#include <cuda_runtime.h>
#include <math_constants.h>

// ---------------------------------------------------------------------------
// EstimatorQNN, 2 qubits, 2 layers — fully fused single kernel.
//
// Algebra: encoded state psi = (c0,s0)(x)(c1,s1); variational circuit = fixed
// 4x4 unitary U(weights); <Z0> = psi^T S psi with S = Re(U^H (Z(x)I) U).
// Double-angle collapse: result = sum of 9 coefficients K over the basis
// {1,cos(pi x0),sin(pi x0)} x {1,cos(pi x1),sin(pi x1)}.
//
// Each block derives K redundantly (threads 0-3 simulate basis columns,
// threads 0-15 reduce S, thread 0 folds to K) while the per-thread input
// loads are in flight, so setup is latency-hidden. One kernel launch.
// Per thread: 8 samples = 4x LDG.128 in, 2x STG.128 out,
//             8x __sincosf + 32 FMA.
// ---------------------------------------------------------------------------

struct Cx { float re, im; };

__device__ __forceinline__ Cx cmul(Cx a, Cx b) {
    Cx r; r.re = a.re * b.re - a.im * b.im; r.im = a.re * b.im + a.im * b.re; return r;
}
__device__ __forceinline__ Cx cadd(Cx a, Cx b) { Cx r; r.re = a.re + b.re; r.im = a.im + b.im; return r; }

__device__ __forceinline__ void apply_gate(Cx s[4], Cx m00, Cx m01, Cx m10, Cx m11, int q) {
    if (q == 0) {
        for (int j = 0; j < 2; j++) {
            Cx a = s[j], b = s[j + 2];
            s[j]     = cadd(cmul(m00, a), cmul(m01, b));
            s[j + 2] = cadd(cmul(m10, a), cmul(m11, b));
        }
    } else {
        for (int j = 0; j < 4; j += 2) {
            Cx a = s[j], b = s[j + 1];
            s[j]     = cadd(cmul(m00, a), cmul(m01, b));
            s[j + 1] = cadd(cmul(m10, a), cmul(m11, b));
        }
    }
}

struct KScratch {
    Cx U[4][4];       // U[k][b]
    float S[4][4];
    float K[9];
};

// Block-level K derivation into sc->K. Three internal __syncthreads.
__device__ void block_build_K(const float* __restrict__ w, KScratch* sc) {
    int t = threadIdx.x;
    if (t < 4) {
        int b = t;
        Cx s[4];
        for (int k = 0; k < 4; k++) { s[k].re = (k == b) ? 1.0f : 0.0f; s[k].im = 0.0f; }
        int off = 0;
        for (int layer = 0; layer < 2; layer++) {
            for (int q = 0; q < 2; q++) {
                float tx = w[off + q * 3 + 0];
                float tz = w[off + q * 3 + 1];
                float ty = w[off + q * 3 + 2];
                float c, sn;
                c = __cosf(0.5f * tx); sn = __sinf(0.5f * tx);
                { Cx m00{c,0}, m01{0,-sn}, m10{0,-sn}, m11{c,0};
                  apply_gate(s, m00, m01, m10, m11, q); }
                c = __cosf(0.5f * tz); sn = __sinf(0.5f * tz);
                { Cx m00{c,-sn}, m01{0,0}, m10{0,0}, m11{c,sn};
                  apply_gate(s, m00, m01, m10, m11, q); }
                c = __cosf(0.5f * ty); sn = __sinf(0.5f * ty);
                { Cx m00{c,0}, m01{-sn,0}, m10{sn,0}, m11{c,0};
                  apply_gate(s, m00, m01, m10, m11, q); }
            }
            Cx tmp = s[2]; s[2] = s[3]; s[3] = tmp;  // CNOT(0->1): swap |10>,|11>
            off += 6;
        }
        for (int k = 0; k < 4; k++) sc->U[k][b] = s[k];
    }
    __syncthreads();
    if (t < 16) {
        int i = t >> 2, j = t & 3;
        float acc = 0.0f;
        for (int k = 0; k < 4; k++) {
            float zk = (k < 2) ? 1.0f : -1.0f;
            acc += zk * (sc->U[k][i].re * sc->U[k][j].re + sc->U[k][i].im * sc->U[k][j].im);
        }
        sc->S[i][j] = acc;
    }
    __syncthreads();
    if (t == 0) {
        float c0 = sc->S[0][0], c1 = sc->S[1][1], c2 = sc->S[2][2], c3 = sc->S[3][3];
        float c4 = 2.0f * sc->S[0][1], c5 = 2.0f * sc->S[0][2], c6 = 2.0f * sc->S[0][3];
        float c7 = 2.0f * sc->S[1][2], c8 = 2.0f * sc->S[1][3], c9 = 2.0f * sc->S[2][3];
        sc->K[0] = 0.25f * (c0 + c1 + c2 + c3);   // 1
        sc->K[1] = 0.25f * (c0 - c1 + c2 - c3);   // C1
        sc->K[2] = 0.25f * (c4 + c9);             // S1
        sc->K[3] = 0.25f * (c0 + c1 - c2 - c3);   // C0
        sc->K[4] = 0.25f * (c0 - c1 - c2 + c3);   // C0*C1
        sc->K[5] = 0.25f * (c4 - c9);             // C0*S1
        sc->K[6] = 0.25f * (c5 + c8);             // S0
        sc->K[7] = 0.25f * (c5 - c8);             // S0*C1
        sc->K[8] = 0.25f * (c6 + c7);             // S0*S1
    }
    __syncthreads();
}

__device__ __forceinline__ float eval_one(float x0, float x1, const float k[9]) {
    float S0, C0, S1, C1;
    __sincosf(CUDART_PI_F * x0, &S0, &C0);
    __sincosf(CUDART_PI_F * x1, &S1, &C1);
    float t1 = fmaf(k[2], S1, fmaf(k[1], C1, k[0]));
    float t2 = fmaf(k[5], S1, fmaf(k[4], C1, k[3]));
    float t3 = fmaf(k[8], S1, fmaf(k[7], C1, k[6]));
    return fmaf(S0, t3, fmaf(C0, t2, t1));
}

// 8 samples per thread: 4x float4 in, 2x float4 out. Fused K derivation.
__global__ void __launch_bounds__(256) qnn_fused_kernel(
    const float4* __restrict__ in, float4* __restrict__ out,
    const float* __restrict__ w, int n_octs) {
    __shared__ KScratch sc;

    int i = blockIdx.x * blockDim.x + threadIdx.x;
    bool valid = (i < n_octs);

    // Issue the long-latency loads FIRST; K derivation hides under them.
    float4 a, b, c, d;
    if (valid) {
        const float4* p = in + 4 * (size_t)i;
        a = p[0]; b = p[1]; c = p[2]; d = p[3];
    }

    block_build_K(w, &sc);

    float k[9];
#pragma unroll
    for (int j = 0; j < 9; j++) k[j] = sc.K[j];

    if (!valid) return;

    float4 r0, r1;
    r0.x = eval_one(a.x, a.y, k);
    r0.y = eval_one(a.z, a.w, k);
    r0.z = eval_one(b.x, b.y, k);
    r0.w = eval_one(b.z, b.w, k);
    r1.x = eval_one(c.x, c.y, k);
    r1.y = eval_one(c.z, c.w, k);
    r1.z = eval_one(d.x, d.y, k);
    r1.w = eval_one(d.z, d.w, k);

    float4* o = out + 2 * (size_t)i;
    o[0] = r0;
    o[1] = r1;
}

// Scalar tail for B % 8 != 0 (not hit for B = 4194304).
__global__ void qnn_tail_kernel(const float2* __restrict__ in,
                                float* __restrict__ out,
                                const float* __restrict__ w, int start, int B) {
    __shared__ KScratch sc;
    block_build_K(w, &sc);
    float k[9];
#pragma unroll
    for (int j = 0; j < 9; j++) k[j] = sc.K[j];
    int i = start + blockIdx.x * blockDim.x + threadIdx.x;
    if (i >= B) return;
    float2 x = in[i];
    out[i] = eval_one(x.x, x.y, k);
}

extern "C" void kernel_launch(void* const* d_in, const int* in_sizes, int n_in,
                              void* d_out, int out_size) {
    const float* inputs  = (const float*)d_in[0];   // [B,2]
    const float* weights = (const float*)d_in[1];   // [12]

    int B = in_sizes[0] / 2;            // 4194304
    int n_octs = B / 8;                 // 524288
    if (n_octs > 0) {
        int threads = 256;
        int blocks = (n_octs + threads - 1) / threads;   // 2048
        qnn_fused_kernel<<<blocks, threads>>>((const float4*)inputs, (float4*)d_out,
                                              weights, n_octs);
    }
    int done = n_octs * 8;
    if (done < B) {
        int rem = B - done;
        qnn_tail_kernel<<<(rem + 127) / 128, 128>>>((const float2*)inputs,
                                                    (float*)d_out, weights, done, B);
    }
}

// round 7
// speedup vs baseline: 1.2083x; 1.2083x over previous
#include <cuda_runtime.h>
#include <math_constants.h>

// ---------------------------------------------------------------------------
// EstimatorQNN, 2 qubits, 2 layers — persistent fused kernel.
//
// Algebra: encoded state psi = (c0,s0)(x)(c1,s1); variational circuit = fixed
// 4x4 unitary U(weights); <Z0> = psi^T S psi, S = Re(U^H (Z(x)I) U).
// Double-angle collapse: result = 9 coefficients K over the basis
// {1,cos(pi x0),sin(pi x0)} x {1,cos(pi x1),sin(pi x1)} -> 2 sincos + 8 FMA.
//
// R6 lessons fixed here:
//  * weights prefetched via 3x float4 BEFORE the gate chain (was: 12 serial
//    dependent LDGs ~3000 cyc -> now one load latency, chain ~500 cyc)
//  * persistent grid (148 SMs x 6 blocks, grid-stride): the per-block K
//    prologue is paid once per resident block (one wave chip-wide), not per
//    wave of a 2048-block launch.
// ---------------------------------------------------------------------------

struct Cx { float re, im; };

__device__ __forceinline__ Cx cmul(Cx a, Cx b) {
    Cx r; r.re = a.re * b.re - a.im * b.im; r.im = a.re * b.im + a.im * b.re; return r;
}
__device__ __forceinline__ Cx cadd(Cx a, Cx b) { Cx r; r.re = a.re + b.re; r.im = a.im + b.im; return r; }

__device__ __forceinline__ void apply_gate(Cx s[4], Cx m00, Cx m01, Cx m10, Cx m11, int q) {
    if (q == 0) {
        for (int j = 0; j < 2; j++) {
            Cx a = s[j], b = s[j + 2];
            s[j]     = cadd(cmul(m00, a), cmul(m01, b));
            s[j + 2] = cadd(cmul(m10, a), cmul(m11, b));
        }
    } else {
        for (int j = 0; j < 4; j += 2) {
            Cx a = s[j], b = s[j + 1];
            s[j]     = cadd(cmul(m00, a), cmul(m01, b));
            s[j + 1] = cadd(cmul(m10, a), cmul(m11, b));
        }
    }
}

struct KScratch {
    Cx U[4][4];       // U[k][b]
    float S[4][4];
    float K[9];
};

// Block-level K derivation into sc->K. Weights are passed in REGISTERS
// (prefetched by the caller) so the gate chain has no memory dependence.
__device__ void block_build_K(const float wr[12], KScratch* sc) {
    int t = threadIdx.x;
    if (t < 4) {
        int b = t;
        Cx s[4];
        for (int k = 0; k < 4; k++) { s[k].re = (k == b) ? 1.0f : 0.0f; s[k].im = 0.0f; }
        int off = 0;
        for (int layer = 0; layer < 2; layer++) {
            for (int q = 0; q < 2; q++) {
                float tx = wr[off + q * 3 + 0];
                float tz = wr[off + q * 3 + 1];
                float ty = wr[off + q * 3 + 2];
                float c, sn;
                c = __cosf(0.5f * tx); sn = __sinf(0.5f * tx);
                { Cx m00{c,0}, m01{0,-sn}, m10{0,-sn}, m11{c,0};
                  apply_gate(s, m00, m01, m10, m11, q); }
                c = __cosf(0.5f * tz); sn = __sinf(0.5f * tz);
                { Cx m00{c,-sn}, m01{0,0}, m10{0,0}, m11{c,sn};
                  apply_gate(s, m00, m01, m10, m11, q); }
                c = __cosf(0.5f * ty); sn = __sinf(0.5f * ty);
                { Cx m00{c,0}, m01{-sn,0}, m10{sn,0}, m11{c,0};
                  apply_gate(s, m00, m01, m10, m11, q); }
            }
            Cx tmp = s[2]; s[2] = s[3]; s[3] = tmp;  // CNOT(0->1): swap |10>,|11>
            off += 6;
        }
        for (int k = 0; k < 4; k++) sc->U[k][b] = s[k];
    }
    __syncthreads();
    if (t < 16) {
        int i = t >> 2, j = t & 3;
        float acc = 0.0f;
        for (int k = 0; k < 4; k++) {
            float zk = (k < 2) ? 1.0f : -1.0f;
            acc += zk * (sc->U[k][i].re * sc->U[k][j].re + sc->U[k][i].im * sc->U[k][j].im);
        }
        sc->S[i][j] = acc;
    }
    __syncthreads();
    if (t == 0) {
        float c0 = sc->S[0][0], c1 = sc->S[1][1], c2 = sc->S[2][2], c3 = sc->S[3][3];
        float c4 = 2.0f * sc->S[0][1], c5 = 2.0f * sc->S[0][2], c6 = 2.0f * sc->S[0][3];
        float c7 = 2.0f * sc->S[1][2], c8 = 2.0f * sc->S[1][3], c9 = 2.0f * sc->S[2][3];
        sc->K[0] = 0.25f * (c0 + c1 + c2 + c3);   // 1
        sc->K[1] = 0.25f * (c0 - c1 + c2 - c3);   // C1
        sc->K[2] = 0.25f * (c4 + c9);             // S1
        sc->K[3] = 0.25f * (c0 + c1 - c2 - c3);   // C0
        sc->K[4] = 0.25f * (c0 - c1 - c2 + c3);   // C0*C1
        sc->K[5] = 0.25f * (c4 - c9);             // C0*S1
        sc->K[6] = 0.25f * (c5 + c8);             // S0
        sc->K[7] = 0.25f * (c5 - c8);             // S0*C1
        sc->K[8] = 0.25f * (c6 + c7);             // S0*S1
    }
    __syncthreads();
}

__device__ __forceinline__ float eval_one(float x0, float x1, const float k[9]) {
    float S0, C0, S1, C1;
    __sincosf(CUDART_PI_F * x0, &S0, &C0);
    __sincosf(CUDART_PI_F * x1, &S1, &C1);
    float t1 = fmaf(k[2], S1, fmaf(k[1], C1, k[0]));
    float t2 = fmaf(k[5], S1, fmaf(k[4], C1, k[3]));
    float t3 = fmaf(k[8], S1, fmaf(k[7], C1, k[6]));
    return fmaf(S0, t3, fmaf(C0, t2, t1));
}

// Persistent kernel. Each block: prefetch weights -> derive K once -> grid-
// stride over tiles of 8 samples/thread (4x float4 in, 2x float4 out).
__global__ void __launch_bounds__(256) qnn_persistent_kernel(
    const float4* __restrict__ in, float4* __restrict__ out,
    const float4* __restrict__ w4, int n_octs) {
    __shared__ KScratch sc;

    // Parallel weight prefetch: one load latency, not 12.
    float4 w0 = w4[0], w1 = w4[1], w2 = w4[2];
    float wr[12] = {w0.x, w0.y, w0.z, w0.w,
                    w1.x, w1.y, w1.z, w1.w,
                    w2.x, w2.y, w2.z, w2.w};

    block_build_K(wr, &sc);

    float k[9];
#pragma unroll
    for (int j = 0; j < 9; j++) k[j] = sc.K[j];

    int stride = gridDim.x * blockDim.x;
    for (int i = blockIdx.x * blockDim.x + threadIdx.x; i < n_octs; i += stride) {
        const float4* p = in + 4 * (size_t)i;
        float4 a = p[0], b = p[1], c = p[2], d = p[3];

        float4 r0, r1;
        r0.x = eval_one(a.x, a.y, k);
        r0.y = eval_one(a.z, a.w, k);
        r0.z = eval_one(b.x, b.y, k);
        r0.w = eval_one(b.z, b.w, k);
        r1.x = eval_one(c.x, c.y, k);
        r1.y = eval_one(c.z, c.w, k);
        r1.z = eval_one(d.x, d.y, k);
        r1.w = eval_one(d.z, d.w, k);

        float4* o = out + 2 * (size_t)i;
        o[0] = r0;
        o[1] = r1;
    }
}

// Scalar tail for B % 8 != 0 (not hit for B = 4194304).
__global__ void qnn_tail_kernel(const float2* __restrict__ in,
                                float* __restrict__ out,
                                const float4* __restrict__ w4, int start, int B) {
    __shared__ KScratch sc;
    float4 w0 = w4[0], w1 = w4[1], w2 = w4[2];
    float wr[12] = {w0.x, w0.y, w0.z, w0.w,
                    w1.x, w1.y, w1.z, w1.w,
                    w2.x, w2.y, w2.z, w2.w};
    block_build_K(wr, &sc);
    float k[9];
#pragma unroll
    for (int j = 0; j < 9; j++) k[j] = sc.K[j];
    int i = start + blockIdx.x * blockDim.x + threadIdx.x;
    if (i >= B) return;
    float2 x = in[i];
    out[i] = eval_one(x.x, x.y, k);
}

extern "C" void kernel_launch(void* const* d_in, const int* in_sizes, int n_in,
                              void* d_out, int out_size) {
    const float* inputs  = (const float*)d_in[0];   // [B,2]
    const float* weights = (const float*)d_in[1];   // [12]

    int B = in_sizes[0] / 2;            // 4194304
    int n_octs = B / 8;                 // 524288
    if (n_octs > 0) {
        int threads = 256;
        // Persistent: one wave on 148 SMs (6 blocks/SM at ~40 regs).
        int blocks = 148 * 6;                            // 888
        int max_needed = (n_octs + threads - 1) / threads;
        if (blocks > max_needed) blocks = max_needed;
        qnn_persistent_kernel<<<blocks, threads>>>((const float4*)inputs,
                                                   (float4*)d_out,
                                                   (const float4*)weights, n_octs);
    }
    int done = n_octs * 8;
    if (done < B) {
        int rem = B - done;
        qnn_tail_kernel<<<(rem + 127) / 128, 128>>>((const float2*)inputs,
                                                    (float*)d_out,
                                                    (const float4*)weights, done, B);
    }
}

// round 9
// speedup vs baseline: 1.3488x; 1.1163x over previous
#include <cuda_runtime.h>
#include <math_constants.h>

// ---------------------------------------------------------------------------
// EstimatorQNN, 2 qubits, 2 layers — persistent fused kernel, R3 tile shape.
//
// Algebra: encoded state psi = (c0,s0)(x)(c1,s1); variational circuit = fixed
// 4x4 unitary U(weights); <Z0> = psi^T S psi, S = Re(U^H (Z(x)I) U).
// Double-angle collapse: result = 9 coefficients K over
// {1,cos(pi x0),sin(pi x0)} x {1,cos(pi x1),sin(pi x1)} -> 2 sincos + 8 FMA.
//
// R7 lessons: occupancy (64.6%, 35 regs, 888 blocks) and the 8-sample tile
// throttled streaming to 2.5 TB/s. This round: 4 samples/thread (2x LDG.128
// + 1x STG.128, the shape that hit 3.6+1.7 TB/s in R3), __launch_bounds__
// (256,8) to force 32 regs / 8 blocks/SM, grid = 148*8 = 1184 persistent
// blocks. K prologue (register-prefetched weights) paid once per block.
// ---------------------------------------------------------------------------

struct Cx { float re, im; };

__device__ __forceinline__ Cx cmul(Cx a, Cx b) {
    Cx r; r.re = a.re * b.re - a.im * b.im; r.im = a.re * b.im + a.im * b.re; return r;
}
__device__ __forceinline__ Cx cadd(Cx a, Cx b) { Cx r; r.re = a.re + b.re; r.im = a.im + b.im; return r; }

__device__ __forceinline__ void apply_gate(Cx s[4], Cx m00, Cx m01, Cx m10, Cx m11, int q) {
    if (q == 0) {
        for (int j = 0; j < 2; j++) {
            Cx a = s[j], b = s[j + 2];
            s[j]     = cadd(cmul(m00, a), cmul(m01, b));
            s[j + 2] = cadd(cmul(m10, a), cmul(m11, b));
        }
    } else {
        for (int j = 0; j < 4; j += 2) {
            Cx a = s[j], b = s[j + 1];
            s[j]     = cadd(cmul(m00, a), cmul(m01, b));
            s[j + 1] = cadd(cmul(m10, a), cmul(m11, b));
        }
    }
}

struct KScratch {
    Cx U[4][4];       // U[k][b]
    float S[4][4];
    float K[9];
};

// Block-level K derivation into sc->K. Weights passed in registers.
__device__ void block_build_K(const float wr[12], KScratch* sc) {
    int t = threadIdx.x;
    if (t < 4) {
        int b = t;
        Cx s[4];
        for (int k = 0; k < 4; k++) { s[k].re = (k == b) ? 1.0f : 0.0f; s[k].im = 0.0f; }
        int off = 0;
        for (int layer = 0; layer < 2; layer++) {
            for (int q = 0; q < 2; q++) {
                float tx = wr[off + q * 3 + 0];
                float tz = wr[off + q * 3 + 1];
                float ty = wr[off + q * 3 + 2];
                float c, sn;
                c = __cosf(0.5f * tx); sn = __sinf(0.5f * tx);
                { Cx m00{c,0}, m01{0,-sn}, m10{0,-sn}, m11{c,0};
                  apply_gate(s, m00, m01, m10, m11, q); }
                c = __cosf(0.5f * tz); sn = __sinf(0.5f * tz);
                { Cx m00{c,-sn}, m01{0,0}, m10{0,0}, m11{c,sn};
                  apply_gate(s, m00, m01, m10, m11, q); }
                c = __cosf(0.5f * ty); sn = __sinf(0.5f * ty);
                { Cx m00{c,0}, m01{-sn,0}, m10{sn,0}, m11{c,0};
                  apply_gate(s, m00, m01, m10, m11, q); }
            }
            Cx tmp = s[2]; s[2] = s[3]; s[3] = tmp;  // CNOT(0->1): swap |10>,|11>
            off += 6;
        }
        for (int k = 0; k < 4; k++) sc->U[k][b] = s[k];
    }
    __syncthreads();
    if (t < 16) {
        int i = t >> 2, j = t & 3;
        float acc = 0.0f;
        for (int k = 0; k < 4; k++) {
            float zk = (k < 2) ? 1.0f : -1.0f;
            acc += zk * (sc->U[k][i].re * sc->U[k][j].re + sc->U[k][i].im * sc->U[k][j].im);
        }
        sc->S[i][j] = acc;
    }
    __syncthreads();
    if (t == 0) {
        float c0 = sc->S[0][0], c1 = sc->S[1][1], c2 = sc->S[2][2], c3 = sc->S[3][3];
        float c4 = 2.0f * sc->S[0][1], c5 = 2.0f * sc->S[0][2], c6 = 2.0f * sc->S[0][3];
        float c7 = 2.0f * sc->S[1][2], c8 = 2.0f * sc->S[1][3], c9 = 2.0f * sc->S[2][3];
        sc->K[0] = 0.25f * (c0 + c1 + c2 + c3);   // 1
        sc->K[1] = 0.25f * (c0 - c1 + c2 - c3);   // C1
        sc->K[2] = 0.25f * (c4 + c9);             // S1
        sc->K[3] = 0.25f * (c0 + c1 - c2 - c3);   // C0
        sc->K[4] = 0.25f * (c0 - c1 - c2 + c3);   // C0*C1
        sc->K[5] = 0.25f * (c4 - c9);             // C0*S1
        sc->K[6] = 0.25f * (c5 + c8);             // S0
        sc->K[7] = 0.25f * (c5 - c8);             // S0*C1
        sc->K[8] = 0.25f * (c6 + c7);             // S0*S1
    }
    __syncthreads();
}

__device__ __forceinline__ float eval_one(float x0, float x1, const float k[9]) {
    float S0, C0, S1, C1;
    __sincosf(CUDART_PI_F * x0, &S0, &C0);
    __sincosf(CUDART_PI_F * x1, &S1, &C1);
    float t1 = fmaf(k[2], S1, fmaf(k[1], C1, k[0]));
    float t2 = fmaf(k[5], S1, fmaf(k[4], C1, k[3]));
    float t3 = fmaf(k[8], S1, fmaf(k[7], C1, k[6]));
    return fmaf(S0, t3, fmaf(C0, t2, t1));
}

// Persistent kernel, 4 samples/thread per iteration: 2x float4 in, 1x float4 out.
__global__ void __launch_bounds__(256, 8) qnn_persistent_kernel(
    const float4* __restrict__ in, float4* __restrict__ out,
    const float4* __restrict__ w4, int n_quads) {
    __shared__ KScratch sc;

    // Parallel weight prefetch: one load latency, not 12.
    float4 w0 = w4[0], w1 = w4[1], w2 = w4[2];
    float wr[12] = {w0.x, w0.y, w0.z, w0.w,
                    w1.x, w1.y, w1.z, w1.w,
                    w2.x, w2.y, w2.z, w2.w};

    block_build_K(wr, &sc);

    float k[9];
#pragma unroll
    for (int j = 0; j < 9; j++) k[j] = sc.K[j];

    int stride = gridDim.x * blockDim.x;
    for (int i = blockIdx.x * blockDim.x + threadIdx.x; i < n_quads; i += stride) {
        float4 a = in[2 * (size_t)i];
        float4 b = in[2 * (size_t)i + 1];
        float4 r;
        r.x = eval_one(a.x, a.y, k);
        r.y = eval_one(a.z, a.w, k);
        r.z = eval_one(b.x, b.y, k);
        r.w = eval_one(b.z, b.w, k);
        out[i] = r;
    }
}

// Scalar tail for B % 4 != 0 (not hit for B = 4194304).
__global__ void qnn_tail_kernel(const float2* __restrict__ in,
                                float* __restrict__ out,
                                const float4* __restrict__ w4, int start, int B) {
    __shared__ KScratch sc;
    float4 w0 = w4[0], w1 = w4[1], w2 = w4[2];
    float wr[12] = {w0.x, w0.y, w0.z, w0.w,
                    w1.x, w1.y, w1.z, w1.w,
                    w2.x, w2.y, w2.z, w2.w};
    block_build_K(wr, &sc);
    float k[9];
#pragma unroll
    for (int j = 0; j < 9; j++) k[j] = sc.K[j];
    int i = start + blockIdx.x * blockDim.x + threadIdx.x;
    if (i >= B) return;
    float2 x = in[i];
    out[i] = eval_one(x.x, x.y, k);
}

extern "C" void kernel_launch(void* const* d_in, const int* in_sizes, int n_in,
                              void* d_out, int out_size) {
    const float* inputs  = (const float*)d_in[0];   // [B,2]
    const float* weights = (const float*)d_in[1];   // [12]

    int B = in_sizes[0] / 2;            // 4194304
    int n_quads = B / 4;                // 1048576
    if (n_quads > 0) {
        int threads = 256;
        int blocks = 148 * 8;                            // 1184: one full wave
        int max_needed = (n_quads + threads - 1) / threads;
        if (blocks > max_needed) blocks = max_needed;
        qnn_persistent_kernel<<<blocks, threads>>>((const float4*)inputs,
                                                   (float4*)d_out,
                                                   (const float4*)weights, n_quads);
    }
    int done = n_quads * 4;
    if (done < B) {
        int rem = B - done;
        qnn_tail_kernel<<<(rem + 127) / 128, 128>>>((const float2*)inputs,
                                                    (float*)d_out,
                                                    (const float4*)weights, done, B);
    }
}